// round 14
// baseline (speedup 1.0000x reference)
#include <cuda_runtime.h>
#include <cuda_bf16.h>
#include <stdint.h>

// Problem constants (fixed by setup_inputs): N=4096 rows, D=512
#define NROW 4096
#define DDIM 512

// symmetric gram tiling: 64x64 block-pairs, upper triangle only
#define BT 64
#define BK 128
#define NIB (NROW / BT)                      // 64 blocks per dim
#define NTILES (NIB * (NIB + 1) / 2)         // 2080 tile pairs
#define GRID 148                             // one CTA per SM (single wave)
#define KCH (DDIM / BK)                      // 4 k-chunks per tile
#define NORM_TILES 14                        // whole tiles per CTA (148*14=2072)
#define NORM_STAGES (NORM_TILES * KCH)       // 56
#define SPECIAL_BASE 2072                    // tiles 2072..2079 are K-split
#define NSPECIAL 8
#define SPECIAL_CTA0 116                     // CTAs 116..147: 1 chunk job each

// stage smem: 4 operand tiles (XI,YI,XJ,YJ) of 64 rows x 256B, XOR-swizzled
// (swizzle applied independently within each 128B half-row)
#define OP_BYTES (BT * 256)                  // 16384
#define STAGE_BYTES (4 * OP_BYTES)           // 65536
#define NSTAGE 3
#define TC_OFF (NSTAGE * STAGE_BYTES)        // 196608
#define SMEM_TOTAL (TC_OFF + 256)            // 196864

#define MR_BLOCKS 128                        // merge_reduce grid

// ---------------- device scratch (allocation-free contract) ----------------
__device__ __align__(16) __nv_bfloat16 g_Xn[NROW * DDIM];
__device__ __align__(16) __nv_bfloat16 g_Yn[NROW * DDIM];
// per tile: row-side partials [tile][wn(2)][row(64)][{l_a,s,l_b}]
__device__ float g_rowpart[NTILES * 2 * BT * 3];
// per tile: col-side partials [tile][wm(4)][col(64)][{l_a,s,l_b}]
__device__ float g_colpart[NTILES * 4 * BT * 3];
// K-split raw partial grams for the 8 remainder tiles
__device__ float g_spart[NSPECIAL][KCH][2][BT * BT];
__device__ float g_bsum[MR_BLOCKS];
__device__ int g_ctr;
__device__ int g_bar;  // monotonic device barrier counter (never reset)

// ---------------- PTX helpers ----------------
__device__ __forceinline__ void ldm_x4(uint32_t &r0, uint32_t &r1, uint32_t &r2,
                                       uint32_t &r3, uint32_t addr) {
  asm volatile("ldmatrix.sync.aligned.m8n8.x4.shared.b16 {%0,%1,%2,%3}, [%4];\n"
               : "=r"(r0), "=r"(r1), "=r"(r2), "=r"(r3)
               : "r"(addr));
}

__device__ __forceinline__ void mma_bf16(float *c, const uint32_t *a,
                                         const uint32_t *b) {
  asm volatile(
      "mma.sync.aligned.m16n8k16.row.col.f32.bf16.bf16.f32 "
      "{%0,%1,%2,%3}, {%4,%5,%6,%7}, {%8,%9}, {%0,%1,%2,%3};\n"
      : "+f"(c[0]), "+f"(c[1]), "+f"(c[2]), "+f"(c[3])
      : "r"(a[0]), "r"(a[1]), "r"(a[2]), "r"(a[3]), "r"(b[0]), "r"(b[1]));
}

__device__ __forceinline__ void cp16(uint32_t saddr, const void *gaddr) {
  asm volatile("cp.async.cg.shared.global [%0], [%1], 16;\n" ::"r"(saddr),
               "l"(gaddr));
}
__device__ __forceinline__ void cp_commit() {
  asm volatile("cp.async.commit_group;\n");
}
template <int N> __device__ __forceinline__ void cp_wait() {
  asm volatile("cp.async.wait_group %0;\n" ::"n"(N));
}

// triangle base index: first tile of strip I
__device__ __host__ __forceinline__ int tri_base(int I) {
  return I * (129 - I) / 2;
}

// ---------------- 1) fused normalize + symmetric gram + KL partials -------
extern __shared__ __align__(16) unsigned char smem_raw[];

__global__ void __launch_bounds__(256, 1) gram_kl_kernel(
    const float *__restrict__ X, const float *__restrict__ Y) {
  const int tid = threadIdx.x;
  const int lane = tid & 31;
  const int wid = tid >> 5;
  const int wm = wid & 3;   // warp row group: rows wm*16
  const int wn = wid >> 2;  // warp col group: cols wn*32
  const int bx = blockIdx.x;

  // ---- phase 0: row-normalize fp32 -> bf16 (warp per row) ----
  for (int m = wid; bx + m * GRID < 2 * NROW; m += 8) {
    const int gr = bx + m * GRID;
    const int row = gr & (NROW - 1);
    const float *src = (gr < NROW) ? X : Y;
    __nv_bfloat16 *dst = (gr < NROW) ? g_Xn : g_Yn;

    const float4 *s4 = reinterpret_cast<const float4 *>(src) + row * (DDIM / 4);
    float4 v[4];
    float ss = 0.f;
#pragma unroll
    for (int q = 0; q < 4; q++) {
      v[q] = s4[lane + 32 * q];
      ss += v[q].x * v[q].x + v[q].y * v[q].y + v[q].z * v[q].z +
            v[q].w * v[q].w;
    }
#pragma unroll
    for (int o = 16; o > 0; o >>= 1) ss += __shfl_xor_sync(0xffffffffu, ss, o);
    const float inv = 1.0f / fmaxf(sqrtf(ss), 1e-8f);

    uint2 *d2 = reinterpret_cast<uint2 *>(dst) + row * (DDIM / 4);
#pragma unroll
    for (int q = 0; q < 4; q++) {
      __nv_bfloat162 p0 = __floats2bfloat162_rn(v[q].x * inv, v[q].y * inv);
      __nv_bfloat162 p1 = __floats2bfloat162_rn(v[q].z * inv, v[q].w * inv);
      uint2 packed;
      packed.x = *reinterpret_cast<uint32_t *>(&p0);
      packed.y = *reinterpret_cast<uint32_t *>(&p1);
      d2[lane + 32 * q] = packed;
    }
  }
  __syncthreads();
  // device-wide barrier: all 148 CTAs resident (1/SM, forced by smem).
  // Monotonic counter; target derived from own arrival -> replay-safe.
  if (tid == 0) {
    __threadfence();
    const int my = atomicAdd(&g_bar, 1);
    const int target = (my / GRID + 1) * GRID;
    while (*((volatile int *)&g_bar) < target) {
    }
    __threadfence();
  }
  __syncthreads();

  // ---- phase 1: gram tiles ----
  const uint32_t sb = (uint32_t)__cvta_generic_to_shared(smem_raw);
  int2 *tc = reinterpret_cast<int2 *>(smem_raw + TC_OFF);

  // chunk-job assignment for the 8 remainder tiles (K split 4 ways)
  const bool has_special = (bx >= SPECIAL_CTA0);
  const int sp = (bx - SPECIAL_CTA0) >> 2;  // special tile index 0..7
  const int ch = (bx - SPECIAL_CTA0) & 3;   // K chunk 0..3

  // 14 whole tiles t = bx + k*GRID (covers 0..2071); entry 14 = special tile
  if (tid < NORM_TILES + 1) {
    int t;
    if (tid < NORM_TILES) t = bx + tid * GRID;
    else if (has_special) t = SPECIAL_BASE + sp;
    else t = 0;  // unused
    int I = 0;
    while (tri_base(I + 1) <= t) I++;
    const int J = I + (t - tri_base(I));
    tc[tid] = make_int2(I * BT, J * BT);
  }
  __syncthreads();

  const int S_ALL = NORM_STAGES + (has_special ? 1 : 0);

  // stage loader: 4 op-tiles x 64 rows x 256B; 16 cp16 per thread
  const int op = tid >> 6;            // 0:XI 1:YI 2:XJ 3:YJ
  const int lhalf = (tid >> 5) & 1;   // which 32-row half of op tile
  const int lrow4 = lane >> 3;        // 0..3
  const int lch = lane & 7;           // 16B chunk within 128B half-row
  const __nv_bfloat16 *lsrc = (op & 1) ? g_Yn : g_Xn;
  const bool iside = (op < 2);

  auto load_stage = [&](int s) {
    if (s < S_ALL) {
      const int k0 = (s >= NORM_STAGES ? ch : (s & 3)) * BK;
      const int2 c = tc[s >> 2];  // s==56 -> entry 14 (special coords)
      const int r0 = iside ? c.x : c.y;
      const uint32_t st = sb + (s % NSTAGE) * STAGE_BYTES + op * OP_BYTES;
#pragma unroll
      for (int it = 0; it < 8; it++) {
        const int row = lhalf * 32 + it * 4 + lrow4;
        const uint32_t rb = st + row * 256 + ((lch ^ (row & 7)) << 4);
        const __nv_bfloat16 *gp = &lsrc[(r0 + row) * DDIM + k0 + lch * 8];
        cp16(rb, gp);                  // half 0 (k elements 0..63)
        cp16(rb + 128, gp + 64);       // half 1 (k elements 64..127)
      }
    }
    cp_commit();  // always commit (group accounting, incl. empty tail groups)
  };

  load_stage(0);
  load_stage(1);

  // fragment coordinates (layouts validated R1/R2)
  const int a_r = wm * 16 + (lane & 15);
  const int a_kc = lane >> 4;                     // k granule offset 0/1
  const int b_r = ((lane >> 4) << 3) + (lane & 7);
  const int b_kc = (lane >> 3) & 1;

  float accA[4][4], accB[4][4];
#pragma unroll
  for (int n = 0; n < 4; n++)
#pragma unroll
    for (int r = 0; r < 4; r++) {
      accA[n][r] = 0.f;
      accB[n][r] = 0.f;
    }

  // one full BK=128 MMA stage on the buffer at smem base `stg`
  auto mma_stage = [&](uint32_t stg) {
    const uint32_t xi_b = stg;
    const uint32_t yi_b = stg + OP_BYTES;
    const uint32_t xj_b = stg + 2 * OP_BYTES;
    const uint32_t yj_b = stg + 3 * OP_BYTES;

    auto load_frags = [&](int kk, uint32_t ax[4], uint32_t ay[4],
                          uint32_t bxf[2][4], uint32_t byf[2][4]) {
      const int ia = (kk >> 3) + a_kc;  // 16B granule index 0..15
      const uint32_t a_off = (uint32_t)(a_r * 256 + ((ia >> 3) << 7) +
                                        (((ia & 7) ^ (a_r & 7)) << 4));
      ldm_x4(ax[0], ax[1], ax[2], ax[3], xi_b + a_off);
      ldm_x4(ay[0], ay[1], ay[2], ay[3], yi_b + a_off);
#pragma unroll
      for (int g = 0; g < 2; g++) {
        const int brow = wn * 32 + g * 16 + b_r;
        const int ib = (kk >> 3) + b_kc;
        const uint32_t b_off = (uint32_t)(brow * 256 + ((ib >> 3) << 7) +
                                          (((ib & 7) ^ (brow & 7)) << 4));
        ldm_x4(bxf[g][0], bxf[g][1], bxf[g][2], bxf[g][3], xj_b + b_off);
        ldm_x4(byf[g][0], byf[g][1], byf[g][2], byf[g][3], yj_b + b_off);
      }
    };

    uint32_t ax[2][4], ay[2][4], bxf[2][2][4], byf[2][2][4];
    load_frags(0, ax[0], ay[0], bxf[0], byf[0]);
#pragma unroll
    for (int kp = 0; kp < 8; kp++) {
      const int cur = kp & 1;
      const int nxt = cur ^ 1;
      if (kp < 7)
        load_frags((kp + 1) * 16, ax[nxt], ay[nxt], bxf[nxt], byf[nxt]);
#pragma unroll
      for (int g = 0; g < 2; g++) {
        mma_bf16(&accA[2 * g + 0][0], ax[cur], &bxf[cur][g][0]);
        mma_bf16(&accA[2 * g + 1][0], ax[cur], &bxf[cur][g][2]);
        mma_bf16(&accB[2 * g + 0][0], ay[cur], &byf[cur][g][0]);
        mma_bf16(&accB[2 * g + 1][0], ay[cur], &byf[cur][g][2]);
      }
    }
  };

  for (int s = 0; s < NORM_STAGES; s++) {
    cp_wait<1>();    // stage s landed (only s+1 left in flight)
    __syncthreads(); // all warps done reading buffer (s-1)%3 before rewrite
    load_stage(s + 2);

    mma_stage(sb + (s % NSTAGE) * STAGE_BYTES);

    if ((s & 3) == 3) {
      // ---- tile epilogue: per-element terms, row sums AND col sums ----
      // logits a=-A, b=-B (bounded in [-1,1], fixed shift 0):
      //   t1=e^{-A}, t2=e^{-A}(B-A), t3=e^{-B}
      const int t_glob = bx + (s >> 2) * GRID;
      float ra[2][3];
      float ca[4][2][3];
#pragma unroll
      for (int h = 0; h < 2; h++)
#pragma unroll
        for (int q = 0; q < 3; q++) ra[h][q] = 0.f;
#pragma unroll
      for (int n = 0; n < 4; n++)
#pragma unroll
        for (int cc = 0; cc < 2; cc++)
#pragma unroll
          for (int q = 0; q < 3; q++) ca[n][cc][q] = 0.f;

#pragma unroll
      for (int n = 0; n < 4; n++)
#pragma unroll
        for (int h = 0; h < 2; h++)
#pragma unroll
          for (int cc = 0; cc < 2; cc++) {
            const float A = accA[n][2 * h + cc];
            const float B = accB[n][2 * h + cc];
            const float e = __expf(-A);
            const float t2 = e * (B - A);
            const float e2 = __expf(-B);
            ra[h][0] += e;
            ra[h][1] += t2;
            ra[h][2] += e2;
            ca[n][cc][0] += e;
            ca[n][cc][1] += t2;
            ca[n][cc][2] += e2;
          }

      // row sums: reduce over the 4 quad lanes (cols)
#pragma unroll
      for (int h = 0; h < 2; h++)
#pragma unroll
        for (int q = 0; q < 3; q++) {
          ra[h][q] += __shfl_xor_sync(0xffffffffu, ra[h][q], 1);
          ra[h][q] += __shfl_xor_sync(0xffffffffu, ra[h][q], 2);
        }
      // col sums: reduce over the 8 row-groups (lane strides 4,8,16)
#pragma unroll
      for (int n = 0; n < 4; n++)
#pragma unroll
        for (int cc = 0; cc < 2; cc++)
#pragma unroll
          for (int q = 0; q < 3; q++) {
            ca[n][cc][q] += __shfl_xor_sync(0xffffffffu, ca[n][cc][q], 4);
            ca[n][cc][q] += __shfl_xor_sync(0xffffffffu, ca[n][cc][q], 8);
            ca[n][cc][q] += __shfl_xor_sync(0xffffffffu, ca[n][cc][q], 16);
          }

      if ((lane & 3) == 0) {
#pragma unroll
        for (int h = 0; h < 2; h++) {
          const int rw = wm * 16 + h * 8 + (lane >> 2);
          float *dst = &g_rowpart[((t_glob * 2 + wn) * BT + rw) * 3];
          dst[0] = ra[h][0];
          dst[1] = ra[h][1];
          dst[2] = ra[h][2];
        }
      }
      if (lane < 4) {
#pragma unroll
        for (int n = 0; n < 4; n++)
#pragma unroll
          for (int cc = 0; cc < 2; cc++) {
            const int cl = wn * 32 + n * 8 + 2 * lane + cc;
            float *dst = &g_colpart[((t_glob * 4 + wm) * BT + cl) * 3];
            dst[0] = ca[n][cc][0];
            dst[1] = ca[n][cc][1];
            dst[2] = ca[n][cc][2];
          }
      }
#pragma unroll
      for (int n = 0; n < 4; n++)
#pragma unroll
        for (int r = 0; r < 4; r++) {
          accA[n][r] = 0.f;
          accB[n][r] = 0.f;
        }
    }
  }

  // ---- cold tail: one K-chunk of a remainder tile; store raw accumulators
  if (has_special) {
    cp_wait<0>();
    __syncthreads();
    mma_stage(sb + (NORM_STAGES % NSTAGE) * STAGE_BYTES);  // buffer 56%3 = 2

    float *pa = g_spart[sp][ch][0];
    float *pb = g_spart[sp][ch][1];
#pragma unroll
    for (int n = 0; n < 4; n++)
#pragma unroll
      for (int h = 0; h < 2; h++)
#pragma unroll
        for (int cc = 0; cc < 2; cc++) {
          const int row = wm * 16 + h * 8 + (lane >> 2);
          const int col = wn * 32 + n * 8 + 2 * (lane & 3) + cc;
          pa[row * BT + col] = accA[n][2 * h + cc];
          pb[row * BT + col] = accB[n][2 * h + cc];
        }
  }
}

// -------- 2) combine the K-split remainder tiles (8 blocks, deterministic)
__global__ void combine_kernel() {
  __shared__ float sA[BT * BT];
  __shared__ float sB[BT * BT];
  const int sp = blockIdx.x;
  const int tid = threadIdx.x;
  const int q = tid & 3;
  const int t = SPECIAL_BASE + sp;

  // reconstruct the full-K gram tiles (fixed chunk order)
  for (int e = tid; e < BT * BT; e += 256) {
    float a = 0.f, b = 0.f;
#pragma unroll
    for (int k = 0; k < KCH; k++) {
      a += g_spart[sp][k][0][e];
      b += g_spart[sp][k][1][e];
    }
    sA[e] = a;
    sB[e] = b;
  }
  __syncthreads();

  // row sums: 4 threads per row, 16 cols each; quad shfl reduce
  {
    const int r = tid >> 2;
    float L = 0.f, S = 0.f, Lb = 0.f;
    for (int c = q * 16; c < q * 16 + 16; c++) {
      const float A = sA[r * BT + c];
      const float B = sB[r * BT + c];
      const float e = __expf(-A);
      L += e;
      S += e * (B - A);
      Lb += __expf(-B);
    }
#pragma unroll
    for (int o = 1; o <= 2; o <<= 1) {
      L += __shfl_xor_sync(0xffffffffu, L, o);
      S += __shfl_xor_sync(0xffffffffu, S, o);
      Lb += __shfl_xor_sync(0xffffffffu, Lb, o);
    }
    if (q == 0) {
      float *d0 = &g_rowpart[((t * 2 + 0) * BT + r) * 3];
      d0[0] = L;
      d0[1] = S;
      d0[2] = Lb;
      float *d1 = &g_rowpart[((t * 2 + 1) * BT + r) * 3];
      d1[0] = 0.f;
      d1[1] = 0.f;
      d1[2] = 0.f;
    }
  }
  // col sums: 4 threads per col, 16 rows each
  {
    const int c = tid >> 2;
    float L = 0.f, S = 0.f, Lb = 0.f;
    for (int r = q * 16; r < q * 16 + 16; r++) {
      const float A = sA[r * BT + c];
      const float B = sB[r * BT + c];
      const float e = __expf(-A);
      L += e;
      S += e * (B - A);
      Lb += __expf(-B);
    }
#pragma unroll
    for (int o = 1; o <= 2; o <<= 1) {
      L += __shfl_xor_sync(0xffffffffu, L, o);
      S += __shfl_xor_sync(0xffffffffu, S, o);
      Lb += __shfl_xor_sync(0xffffffffu, Lb, o);
    }
    if (q == 0) {
      float *d0 = &g_colpart[((t * 4 + 0) * BT + c) * 3];
      d0[0] = L;
      d0[1] = S;
      d0[2] = Lb;
#pragma unroll
      for (int w = 1; w < 4; w++) {
        float *dz = &g_colpart[((t * 4 + w) * BT + c) * 3];
        dz[0] = 0.f;
        dz[1] = 0.f;
        dz[2] = 0.f;
      }
    }
  }
}

// -------- 3) merge per-row partials + fused deterministic mean ----------
// 128 blocks x 256 threads; 8 threads cooperate per row (32 rows per block).
__global__ void merge_reduce_kernel(float *__restrict__ out) {
  __shared__ float red[32];
  const int tid = threadIdx.x;
  const int lane = tid & 31;
  const int q = tid & 7;                       // slot phase within row group
  const int r = blockIdx.x * 32 + (tid >> 3);  // global row
  const int I = r >> 6;
  const int ri = r & 63;
  float L = 0.f, S = 0.f, Lb = 0.f;

  // row-side contributions: tiles (I, J) for J >= I; 2 slots per tile
  const int cnt1 = 2 * (NIB - I);
  const int tb = tri_base(I);
  for (int u = q; u < cnt1; u += 8) {
    const int t = tb + (u >> 1);
    const int w = u & 1;
    const float *p = &g_rowpart[((t * 2 + w) * BT + ri) * 3];
    L += p[0];
    S += p[1];
    Lb += p[2];
  }
  // col-side contributions: tiles (K, I) for K < I; 4 slots per tile
  const int cnt2 = 4 * I;
  for (int u = q; u < cnt2; u += 8) {
    const int K = u >> 2;
    const int w = u & 3;
    const int tt = tri_base(K) + (I - K);
    const float *p = &g_colpart[((tt * 4 + w) * BT + ri) * 3];
    L += p[0];
    S += p[1];
    Lb += p[2];
  }

  // 8-lane segmented reduce (fixed order)
#pragma unroll
  for (int o = 1; o <= 4; o <<= 1) {
    L += __shfl_xor_sync(0xffffffffu, L, o);
    S += __shfl_xor_sync(0xffffffffu, S, o);
    Lb += __shfl_xor_sync(0xffffffffu, Lb, o);
  }

  // group leader: kl_r = sum t*(a-b) - lse(a) + lse(b), fixed shift 0
  float kl = 0.f;
  if (q == 0) kl = S / L - logf(L) + logf(Lb);
  // warp: sum the 4 leaders' kl values (lanes 0,8,16,24), fixed order
#pragma unroll
  for (int o = 8; o <= 16; o <<= 1) kl += __shfl_xor_sync(0xffffffffu, kl, o);
  if (lane == 0) red[tid >> 5] = kl;
  __syncthreads();

  // warp 0: sum 8 warp partials (fixed order), then last-block combine
  if (tid < 32) {
    float v = (lane < 8) ? red[lane] : 0.f;
#pragma unroll
    for (int o = 1; o <= 4; o <<= 1) v += __shfl_xor_sync(0xffffffffu, v, o);
    if (lane == 0) {
      g_bsum[blockIdx.x] = v;
      __threadfence();
      const int prev = atomicAdd(&g_ctr, 1);
      if (prev == MR_BLOCKS - 1) {  // last block: finish the mean
        float s = 0.f;
        for (int k = 0; k < MR_BLOCKS; k++) {
          s += *((volatile float *)&g_bsum[k]);
        }
        out[0] = s / (float)NROW;
        atomicExch(&g_ctr, 0);  // reset for next graph replay
      }
    }
  }
}

// ---------------- launch ----------------
extern "C" void kernel_launch(void *const *d_in, const int *in_sizes, int n_in,
                              void *d_out, int out_size) {
  const float *X = (const float *)d_in[0];  // cosine_distance_latent (target)
  const float *Y = (const float *)d_in[1];  // mse_latent (predicted)
  float *out = (float *)d_out;

  cudaFuncSetAttribute(gram_kl_kernel,
                       cudaFuncAttributeMaxDynamicSharedMemorySize, SMEM_TOTAL);

  gram_kl_kernel<<<GRID, 256, SMEM_TOTAL>>>(X, Y);
  combine_kernel<<<NSPECIAL, 256>>>();
  merge_reduce_kernel<<<MR_BLOCKS, 256>>>(out);
}

// round 15
// speedup vs baseline: 1.1387x; 1.1387x over previous
#include <cuda_runtime.h>
#include <cuda_bf16.h>
#include <stdint.h>

// Problem constants (fixed by setup_inputs): N=4096 rows, D=512
#define NROW 4096
#define DDIM 512

// symmetric gram tiling: 64x64 block-pairs, upper triangle only
#define BT 64
#define BK 64
#define NIB (NROW / BT)                      // 64 blocks per dim
#define NTILES (NIB * (NIB + 1) / 2)         // 2080 tile pairs
#define GRID 296                             // two CTAs per SM
#define KCH (DDIM / BK)                      // 8 k-chunks per tile
#define MAXT 8                               // ceil(2080/296)

// stage smem: 4 operand tiles (XI,YI,XJ,YJ) of 64 rows x 128B, XOR-swizzled
#define OP_BYTES (BT * 128)                  // 8192
#define STAGE_BYTES (4 * OP_BYTES)           // 32768
#define NSTAGE 3
#define TC_OFF (NSTAGE * STAGE_BYTES)        // 98304
#define SMEM_TOTAL (TC_OFF + 256)            // 98560 (2 per SM fits 228KB)

#define MR_BLOCKS 128                        // merge_reduce grid

// ---------------- device scratch (allocation-free contract) ----------------
__device__ __align__(16) __nv_bfloat16 g_Xn[NROW * DDIM];
__device__ __align__(16) __nv_bfloat16 g_Yn[NROW * DDIM];
// per tile: row-side partials [tile][wn(2)][row(64)][{l_a,s,l_b}]
__device__ float g_rowpart[NTILES * 2 * BT * 3];
// per tile: col-side partials [tile][wm(4)][col(64)][{l_a,s,l_b}]
__device__ float g_colpart[NTILES * 4 * BT * 3];
__device__ float g_bsum[MR_BLOCKS];
__device__ int g_ctr;

// ---------------- PTX helpers ----------------
__device__ __forceinline__ void ldm_x4(uint32_t &r0, uint32_t &r1, uint32_t &r2,
                                       uint32_t &r3, uint32_t addr) {
  asm volatile("ldmatrix.sync.aligned.m8n8.x4.shared.b16 {%0,%1,%2,%3}, [%4];\n"
               : "=r"(r0), "=r"(r1), "=r"(r2), "=r"(r3)
               : "r"(addr));
}

__device__ __forceinline__ void mma_bf16(float *c, const uint32_t *a,
                                         const uint32_t *b) {
  asm volatile(
      "mma.sync.aligned.m16n8k16.row.col.f32.bf16.bf16.f32 "
      "{%0,%1,%2,%3}, {%4,%5,%6,%7}, {%8,%9}, {%0,%1,%2,%3};\n"
      : "+f"(c[0]), "+f"(c[1]), "+f"(c[2]), "+f"(c[3])
      : "r"(a[0]), "r"(a[1]), "r"(a[2]), "r"(a[3]), "r"(b[0]), "r"(b[1]));
}

__device__ __forceinline__ void cp16(uint32_t saddr, const void *gaddr) {
  asm volatile("cp.async.cg.shared.global [%0], [%1], 16;\n" ::"r"(saddr),
               "l"(gaddr));
}
__device__ __forceinline__ void cp_commit() {
  asm volatile("cp.async.commit_group;\n");
}
template <int N> __device__ __forceinline__ void cp_wait() {
  asm volatile("cp.async.wait_group %0;\n" ::"n"(N));
}

// triangle base index: first tile of strip I
__device__ __host__ __forceinline__ int tri_base(int I) {
  return I * (129 - I) / 2;
}

// ---------------- 1) row-normalize fp32 -> bf16 (warp per row) ------------
__global__ void normalize_kernel(const float *__restrict__ X,
                                 const float *__restrict__ Y) {
  const int gw = (blockIdx.x * blockDim.x + threadIdx.x) >> 5;  // 0..8191
  const int lane = threadIdx.x & 31;
  const int row = gw & (NROW - 1);
  const float *src = (gw < NROW) ? X : Y;
  __nv_bfloat16 *dst = (gw < NROW) ? g_Xn : g_Yn;

  const float4 *s4 = reinterpret_cast<const float4 *>(src) + row * (DDIM / 4);
  float4 v[4];
  float ss = 0.f;
#pragma unroll
  for (int q = 0; q < 4; q++) {
    v[q] = s4[lane + 32 * q];
    ss += v[q].x * v[q].x + v[q].y * v[q].y + v[q].z * v[q].z + v[q].w * v[q].w;
  }
#pragma unroll
  for (int o = 16; o > 0; o >>= 1) ss += __shfl_xor_sync(0xffffffffu, ss, o);
  const float inv = 1.0f / fmaxf(sqrtf(ss), 1e-8f);

  uint2 *d2 = reinterpret_cast<uint2 *>(dst) + row * (DDIM / 4);
#pragma unroll
  for (int q = 0; q < 4; q++) {
    __nv_bfloat162 p0 = __floats2bfloat162_rn(v[q].x * inv, v[q].y * inv);
    __nv_bfloat162 p1 = __floats2bfloat162_rn(v[q].z * inv, v[q].w * inv);
    uint2 packed;
    packed.x = *reinterpret_cast<uint32_t *>(&p0);
    packed.y = *reinterpret_cast<uint32_t *>(&p1);
    d2[lane + 32 * q] = packed;
  }
}

// ---------------- 2) symmetric gram + softmax-KL partials ----------------
extern __shared__ __align__(16) unsigned char smem_raw[];

__global__ void __launch_bounds__(256, 2) gram_kl_kernel() {
  const int tid = threadIdx.x;
  const int lane = tid & 31;
  const int wid = tid >> 5;
  const int wm = wid & 3;   // warp row group: rows wm*16
  const int wn = wid >> 2;  // warp col group: cols wn*32
  const int bx = blockIdx.x;

  const uint32_t sb = (uint32_t)__cvta_generic_to_shared(smem_raw);
  int2 *tc = reinterpret_cast<int2 *>(smem_raw + TC_OFF);

  // tiles for this CTA: t = bx + k*GRID, k = 0..ntiles-1
  const int ntiles = (NTILES - 1 - bx) / GRID + 1;
  if (tid < ntiles) {
    const int t = bx + tid * GRID;
    int I = 0;
    while (tri_base(I + 1) <= t) I++;
    const int J = I + (t - tri_base(I));
    tc[tid] = make_int2(I * BT, J * BT);
  }
  __syncthreads();

  const int S_ALL = ntiles * KCH;

  // stage loader: 4 op-tiles x 64 rows x 128B; warp covers 4 rows x 8 chunks
  const int op = tid >> 6;            // 0:XI 1:YI 2:XJ 3:YJ
  const int lhalf = (tid >> 5) & 1;   // which 32-row half of op tile
  const int lrow4 = lane >> 3;        // 0..3
  const int lch = lane & 7;           // 16B chunk within row
  const __nv_bfloat16 *lsrc = (op & 1) ? g_Yn : g_Xn;
  const bool iside = (op < 2);

  auto load_stage = [&](int s) {
    if (s < S_ALL) {
      const int k0 = (s & 7) * BK;
      const int2 c = tc[s >> 3];
      const int r0 = iside ? c.x : c.y;
      const uint32_t st = sb + (s % NSTAGE) * STAGE_BYTES + op * OP_BYTES;
#pragma unroll
      for (int it = 0; it < 8; it++) {
        const int row = lhalf * 32 + it * 4 + lrow4;
        const uint32_t sa = st + row * 128 + ((lch ^ (row & 7)) << 4);
        cp16(sa, &lsrc[(r0 + row) * DDIM + k0 + lch * 8]);
      }
    }
    cp_commit();  // always commit (group accounting, incl. empty tail groups)
  };

  load_stage(0);
  load_stage(1);

  // fragment coordinates (layouts validated R1/R2/R8)
  const int a_r = wm * 16 + (lane & 15);
  const int a_kc = lane >> 4;                     // k granule offset 0/1
  const int b_r = ((lane >> 4) << 3) + (lane & 7);
  const int b_kc = (lane >> 3) & 1;

  float accA[4][4], accB[4][4];
#pragma unroll
  for (int n = 0; n < 4; n++)
#pragma unroll
    for (int r = 0; r < 4; r++) {
      accA[n][r] = 0.f;
      accB[n][r] = 0.f;
    }

  for (int s = 0; s < S_ALL; s++) {
    cp_wait<1>();    // stage s landed (only s+1 left in flight)
    __syncthreads(); // all warps done reading buffer (s-1)%3 before rewrite
    load_stage(s + 2);

    const uint32_t stg = sb + (s % NSTAGE) * STAGE_BYTES;
    const uint32_t xi_b = stg;
    const uint32_t yi_b = stg + OP_BYTES;
    const uint32_t xj_b = stg + 2 * OP_BYTES;
    const uint32_t yj_b = stg + 3 * OP_BYTES;

    // fragment loader for one kk granule (kk in 0,16,32,48)
    auto load_frags = [&](int kk, uint32_t ax[4], uint32_t ay[4],
                          uint32_t bxf[2][4], uint32_t byf[2][4]) {
      const uint32_t a_sw = (uint32_t)((((kk >> 3) + a_kc) ^ (a_r & 7)) << 4);
      ldm_x4(ax[0], ax[1], ax[2], ax[3], xi_b + a_r * 128 + a_sw);
      ldm_x4(ay[0], ay[1], ay[2], ay[3], yi_b + a_r * 128 + a_sw);
#pragma unroll
      for (int g = 0; g < 2; g++) {
        const int brow = wn * 32 + g * 16 + b_r;
        const uint32_t b_sw =
            (uint32_t)((((kk >> 3) + b_kc) ^ (brow & 7)) << 4);
        ldm_x4(bxf[g][0], bxf[g][1], bxf[g][2], bxf[g][3],
               xj_b + brow * 128 + b_sw);
        ldm_x4(byf[g][0], byf[g][1], byf[g][2], byf[g][3],
               yj_b + brow * 128 + b_sw);
      }
    };

    // software pipeline over the 4 kk granules (double-buffered fragments)
    uint32_t ax[2][4], ay[2][4], bxf[2][2][4], byf[2][2][4];
    load_frags(0, ax[0], ay[0], bxf[0], byf[0]);
#pragma unroll
    for (int kp = 0; kp < 4; kp++) {
      const int cur = kp & 1;
      const int nxt = cur ^ 1;
      if (kp < 3) load_frags((kp + 1) * 16, ax[nxt], ay[nxt], bxf[nxt], byf[nxt]);
#pragma unroll
      for (int g = 0; g < 2; g++) {
        mma_bf16(&accA[2 * g + 0][0], ax[cur], &bxf[cur][g][0]);
        mma_bf16(&accA[2 * g + 1][0], ax[cur], &bxf[cur][g][2]);
        mma_bf16(&accB[2 * g + 0][0], ay[cur], &byf[cur][g][0]);
        mma_bf16(&accB[2 * g + 1][0], ay[cur], &byf[cur][g][2]);
      }
    }

    if ((s & 7) == 7) {
      // ---- tile epilogue: per-element terms, row sums AND col sums ----
      // logits a=-A, b=-B (bounded in [-1,1], fixed shift 0):
      //   t1=e^{-A}, t2=e^{-A}(B-A), t3=e^{-B}
      const int t_glob = bx + (s >> 3) * GRID;
      float ra[2][3];
      float ca[4][2][3];
#pragma unroll
      for (int h = 0; h < 2; h++)
#pragma unroll
        for (int q = 0; q < 3; q++) ra[h][q] = 0.f;
#pragma unroll
      for (int n = 0; n < 4; n++)
#pragma unroll
        for (int cc = 0; cc < 2; cc++)
#pragma unroll
          for (int q = 0; q < 3; q++) ca[n][cc][q] = 0.f;

#pragma unroll
      for (int n = 0; n < 4; n++)
#pragma unroll
        for (int h = 0; h < 2; h++)
#pragma unroll
          for (int cc = 0; cc < 2; cc++) {
            const float A = accA[n][2 * h + cc];
            const float B = accB[n][2 * h + cc];
            const float e = __expf(-A);
            const float t2 = e * (B - A);
            const float e2 = __expf(-B);
            ra[h][0] += e;
            ra[h][1] += t2;
            ra[h][2] += e2;
            ca[n][cc][0] += e;
            ca[n][cc][1] += t2;
            ca[n][cc][2] += e2;
          }

      // row sums: reduce over the 4 quad lanes (cols)
#pragma unroll
      for (int h = 0; h < 2; h++)
#pragma unroll
        for (int q = 0; q < 3; q++) {
          ra[h][q] += __shfl_xor_sync(0xffffffffu, ra[h][q], 1);
          ra[h][q] += __shfl_xor_sync(0xffffffffu, ra[h][q], 2);
        }
      // col sums: reduce over the 8 row-groups (lane strides 4,8,16)
#pragma unroll
      for (int n = 0; n < 4; n++)
#pragma unroll
        for (int cc = 0; cc < 2; cc++)
#pragma unroll
          for (int q = 0; q < 3; q++) {
            ca[n][cc][q] += __shfl_xor_sync(0xffffffffu, ca[n][cc][q], 4);
            ca[n][cc][q] += __shfl_xor_sync(0xffffffffu, ca[n][cc][q], 8);
            ca[n][cc][q] += __shfl_xor_sync(0xffffffffu, ca[n][cc][q], 16);
          }

      if ((lane & 3) == 0) {
#pragma unroll
        for (int h = 0; h < 2; h++) {
          const int rw = wm * 16 + h * 8 + (lane >> 2);
          float *dst = &g_rowpart[((t_glob * 2 + wn) * BT + rw) * 3];
          dst[0] = ra[h][0];
          dst[1] = ra[h][1];
          dst[2] = ra[h][2];
        }
      }
      if (lane < 4) {
#pragma unroll
        for (int n = 0; n < 4; n++)
#pragma unroll
          for (int cc = 0; cc < 2; cc++) {
            const int cl = wn * 32 + n * 8 + 2 * lane + cc;
            float *dst = &g_colpart[((t_glob * 4 + wm) * BT + cl) * 3];
            dst[0] = ca[n][cc][0];
            dst[1] = ca[n][cc][1];
            dst[2] = ca[n][cc][2];
          }
      }
#pragma unroll
      for (int n = 0; n < 4; n++)
#pragma unroll
        for (int r = 0; r < 4; r++) {
          accA[n][r] = 0.f;
          accB[n][r] = 0.f;
        }
    }
  }
}

// -------- 3) merge per-row partials + fused deterministic mean ----------
// 128 blocks x 256 threads; 8 threads cooperate per row (32 rows per block).
__global__ void merge_reduce_kernel(float *__restrict__ out) {
  __shared__ float red[32];
  const int tid = threadIdx.x;
  const int lane = tid & 31;
  const int q = tid & 7;                       // slot phase within row group
  const int r = blockIdx.x * 32 + (tid >> 3);  // global row
  const int I = r >> 6;
  const int ri = r & 63;
  float L = 0.f, S = 0.f, Lb = 0.f;

  // row-side contributions: tiles (I, J) for J >= I; 2 slots per tile
  const int cnt1 = 2 * (NIB - I);
  const int tb = tri_base(I);
  for (int u = q; u < cnt1; u += 8) {
    const int t = tb + (u >> 1);
    const int w = u & 1;
    const float *p = &g_rowpart[((t * 2 + w) * BT + ri) * 3];
    L += p[0];
    S += p[1];
    Lb += p[2];
  }
  // col-side contributions: tiles (K, I) for K < I; 4 slots per tile
  const int cnt2 = 4 * I;
  for (int u = q; u < cnt2; u += 8) {
    const int K = u >> 2;
    const int w = u & 3;
    const int tt = tri_base(K) + (I - K);
    const float *p = &g_colpart[((tt * 4 + w) * BT + ri) * 3];
    L += p[0];
    S += p[1];
    Lb += p[2];
  }

  // 8-lane segmented reduce (fixed order)
#pragma unroll
  for (int o = 1; o <= 4; o <<= 1) {
    L += __shfl_xor_sync(0xffffffffu, L, o);
    S += __shfl_xor_sync(0xffffffffu, S, o);
    Lb += __shfl_xor_sync(0xffffffffu, Lb, o);
  }

  // group leader: kl_r = sum t*(a-b) - lse(a) + lse(b), fixed shift 0
  float kl = 0.f;
  if (q == 0) kl = S / L - logf(L) + logf(Lb);
  // warp: sum the 4 leaders' kl values (lanes 0,8,16,24), fixed order
#pragma unroll
  for (int o = 8; o <= 16; o <<= 1) kl += __shfl_xor_sync(0xffffffffu, kl, o);
  if (lane == 0) red[tid >> 5] = kl;
  __syncthreads();

  // warp 0: sum 8 warp partials (fixed order), then last-block combine
  if (tid < 32) {
    float v = (lane < 8) ? red[lane] : 0.f;
#pragma unroll
    for (int o = 1; o <= 4; o <<= 1) v += __shfl_xor_sync(0xffffffffu, v, o);
    if (lane == 0) {
      g_bsum[blockIdx.x] = v;
      __threadfence();
      const int prev = atomicAdd(&g_ctr, 1);
      if (prev == MR_BLOCKS - 1) {  // last block: finish the mean
        float s = 0.f;
        for (int k = 0; k < MR_BLOCKS; k++) {
          s += *((volatile float *)&g_bsum[k]);
        }
        out[0] = s / (float)NROW;
        atomicExch(&g_ctr, 0);  // reset for next graph replay
      }
    }
  }
}

// ---------------- launch ----------------
extern "C" void kernel_launch(void *const *d_in, const int *in_sizes, int n_in,
                              void *d_out, int out_size) {
  const float *X = (const float *)d_in[0];  // cosine_distance_latent (target)
  const float *Y = (const float *)d_in[1];  // mse_latent (predicted)
  float *out = (float *)d_out;

  cudaFuncSetAttribute(gram_kl_kernel,
                       cudaFuncAttributeMaxDynamicSharedMemorySize, SMEM_TOTAL);

  normalize_kernel<<<1024, 256>>>(X, Y);
  gram_kl_kernel<<<GRID, 256, SMEM_TOTAL>>>();
  merge_reduce_kernel<<<MR_BLOCKS, 256>>>(out);
}

// round 16
// speedup vs baseline: 1.3229x; 1.1618x over previous
#include <cuda_runtime.h>
#include <cuda_bf16.h>
#include <stdint.h>

// Problem constants (fixed by setup_inputs): N=4096 rows, D=512
#define NROW 4096
#define DDIM 512

// symmetric gram tiling: 64x64 block-pairs, upper triangle only
#define BT 64
#define BK 64
#define NIB (NROW / BT)                      // 64 blocks per dim
#define NTILES (NIB * (NIB + 1) / 2)         // 2080 tile pairs
#define GRID 296                             // two CTAs per SM
#define KCH (DDIM / BK)                      // 8 k-chunks per tile
#define MAXT 8                               // ceil(2080/296)

// stage smem: 4 operand tiles (XI,YI,XJ,YJ) of 64 rows x 128B, XOR-swizzled
#define OP_BYTES (BT * 128)                  // 8192
#define STAGE_BYTES (4 * OP_BYTES)           // 32768
#define NSTAGE 3
#define TC_OFF (NSTAGE * STAGE_BYTES)        // 98304
#define SMEM_TOTAL (TC_OFF + 256)            // 98560 (2 per SM fits)

// epilogue exchange: 4 slabs of 32x33 fp32 inside the free ring buffer
#define EX_SLAB (32 * 33)                    // floats per warp slab (4224B)

#define MR_BLOCKS 128                        // merge_reduce grid

// ---------------- device scratch (allocation-free contract) ----------------
__device__ __align__(16) __nv_bfloat16 g_Xn[NROW * DDIM];
__device__ __align__(16) __nv_bfloat16 g_Yn[NROW * DDIM];
// per tile: row-side partials [tile][wn(2)][row(64)][{l_a,s,l_b}]
__device__ float g_rowpart[NTILES * 2 * BT * 3];
// per tile: col-side partials [tile][wm(2)][col(64)][{l_a,s,l_b}]
__device__ float g_colpart[NTILES * 2 * BT * 3];
__device__ float g_bsum[MR_BLOCKS];
__device__ int g_ctr;

// ---------------- PTX helpers ----------------
__device__ __forceinline__ void ldm_x4(uint32_t &r0, uint32_t &r1, uint32_t &r2,
                                       uint32_t &r3, uint32_t addr) {
  asm volatile("ldmatrix.sync.aligned.m8n8.x4.shared.b16 {%0,%1,%2,%3}, [%4];\n"
               : "=r"(r0), "=r"(r1), "=r"(r2), "=r"(r3)
               : "r"(addr));
}

__device__ __forceinline__ void mma_bf16(float *c, const uint32_t *a,
                                         const uint32_t *b) {
  asm volatile(
      "mma.sync.aligned.m16n8k16.row.col.f32.bf16.bf16.f32 "
      "{%0,%1,%2,%3}, {%4,%5,%6,%7}, {%8,%9}, {%0,%1,%2,%3};\n"
      : "+f"(c[0]), "+f"(c[1]), "+f"(c[2]), "+f"(c[3])
      : "r"(a[0]), "r"(a[1]), "r"(a[2]), "r"(a[3]), "r"(b[0]), "r"(b[1]));
}

__device__ __forceinline__ void cp16(uint32_t saddr, const void *gaddr) {
  asm volatile("cp.async.cg.shared.global [%0], [%1], 16;\n" ::"r"(saddr),
               "l"(gaddr));
}
__device__ __forceinline__ void cp_commit() {
  asm volatile("cp.async.commit_group;\n");
}
template <int N> __device__ __forceinline__ void cp_wait() {
  asm volatile("cp.async.wait_group %0;\n" ::"n"(N));
}

// triangle base index: first tile of strip I
__device__ __host__ __forceinline__ int tri_base(int I) {
  return I * (129 - I) / 2;
}

// ---------------- 1) row-normalize fp32 -> bf16 (warp per row) ------------
__global__ void normalize_kernel(const float *__restrict__ X,
                                 const float *__restrict__ Y) {
  const int gw = (blockIdx.x * blockDim.x + threadIdx.x) >> 5;  // 0..8191
  const int lane = threadIdx.x & 31;
  const int row = gw & (NROW - 1);
  const float *src = (gw < NROW) ? X : Y;
  __nv_bfloat16 *dst = (gw < NROW) ? g_Xn : g_Yn;

  const float4 *s4 = reinterpret_cast<const float4 *>(src) + row * (DDIM / 4);
  float4 v[4];
  float ss = 0.f;
#pragma unroll
  for (int q = 0; q < 4; q++) {
    v[q] = s4[lane + 32 * q];
    ss += v[q].x * v[q].x + v[q].y * v[q].y + v[q].z * v[q].z + v[q].w * v[q].w;
  }
#pragma unroll
  for (int o = 16; o > 0; o >>= 1) ss += __shfl_xor_sync(0xffffffffu, ss, o);
  const float inv = 1.0f / fmaxf(sqrtf(ss), 1e-8f);

  uint2 *d2 = reinterpret_cast<uint2 *>(dst) + row * (DDIM / 4);
#pragma unroll
  for (int q = 0; q < 4; q++) {
    __nv_bfloat162 p0 = __floats2bfloat162_rn(v[q].x * inv, v[q].y * inv);
    __nv_bfloat162 p1 = __floats2bfloat162_rn(v[q].z * inv, v[q].w * inv);
    uint2 packed;
    packed.x = *reinterpret_cast<uint32_t *>(&p0);
    packed.y = *reinterpret_cast<uint32_t *>(&p1);
    d2[lane + 32 * q] = packed;
  }
}

// ---------------- 2) symmetric gram + softmax-KL partials ----------------
// Warps 0-3: gram X (32x32 tiles, 2x2 grid). Warps 4-7: gram Y (same map).
// Epilogue: Y-warps stage acc into the free ring buffer; X-warps pair & sum.
extern __shared__ __align__(16) unsigned char smem_raw[];

__global__ void __launch_bounds__(256, 2) gram_kl_kernel() {
  const int tid = threadIdx.x;
  const int lane = tid & 31;
  const int wid = tid >> 5;
  const int widg = wid & 3;       // warp tile id within gram group
  const bool isX = (wid < 4);     // gram X warps vs gram Y warps
  const int wm = widg >> 1;       // warp row group: rows wm*32
  const int wn = widg & 1;        // warp col group: cols wn*32
  const int bx = blockIdx.x;

  const uint32_t sb = (uint32_t)__cvta_generic_to_shared(smem_raw);
  int2 *tc = reinterpret_cast<int2 *>(smem_raw + TC_OFF);

  // tiles for this CTA: t = bx + k*GRID, k = 0..ntiles-1
  const int ntiles = (NTILES - 1 - bx) / GRID + 1;
  if (tid < ntiles) {
    const int t = bx + tid * GRID;
    int I = 0;
    while (tri_base(I + 1) <= t) I++;
    const int J = I + (t - tri_base(I));
    tc[tid] = make_int2(I * BT, J * BT);
  }
  __syncthreads();

  const int S_ALL = ntiles * KCH;

  // stage loader: 4 op-tiles x 64 rows x 128B; warp covers 4 rows x 8 chunks
  const int op = tid >> 6;            // 0:XI 1:YI 2:XJ 3:YJ
  const int lhalf = (tid >> 5) & 1;   // which 32-row half of op tile
  const int lrow4 = lane >> 3;        // 0..3
  const int lch = lane & 7;           // 16B chunk within row
  const __nv_bfloat16 *lsrc = (op & 1) ? g_Yn : g_Xn;
  const bool iside = (op < 2);

  auto load_stage = [&](int s) {
    if (s < S_ALL) {
      const int k0 = (s & 7) * BK;
      const int2 c = tc[s >> 3];
      const int r0 = iside ? c.x : c.y;
      const uint32_t st = sb + (s % NSTAGE) * STAGE_BYTES + op * OP_BYTES;
#pragma unroll
      for (int it = 0; it < 8; it++) {
        const int row = lhalf * 32 + it * 4 + lrow4;
        const uint32_t sa = st + row * 128 + ((lch ^ (row & 7)) << 4);
        cp16(sa, &lsrc[(r0 + row) * DDIM + k0 + lch * 8]);
      }
    }
    cp_commit();  // always commit (group accounting, incl. empty tail groups)
  };

  load_stage(0);
  load_stage(1);

  // fragment coordinates (layouts validated R1/R2/R5/R8)
  const int a_r = wm * 32 + (lane & 15);          // A rows (mf adds +16)
  const int a_kc = lane >> 4;                     // k granule offset 0/1
  const int b_r = ((lane >> 4) << 3) + (lane & 7);
  const int b_kc = (lane >> 3) & 1;

  // single-gram accumulator: 32x32 warp tile -> [mf(2)][n(4)][4]
  float acc[2][4][4];
#pragma unroll
  for (int mf = 0; mf < 2; mf++)
#pragma unroll
    for (int n = 0; n < 4; n++)
#pragma unroll
      for (int r = 0; r < 4; r++) acc[mf][n][r] = 0.f;

  for (int s = 0; s < S_ALL; s++) {
    cp_wait<1>();    // stage s landed (only s+1 left in flight)
    __syncthreads(); // all warps done reading buffer (s-1)%3 before rewrite
    load_stage(s + 2);

    const uint32_t stg = sb + (s % NSTAGE) * STAGE_BYTES;
    // this warp's gram selects its operand pair
    const uint32_t i_b = stg + (isX ? 0 : OP_BYTES);              // XI or YI
    const uint32_t j_b = stg + 2 * OP_BYTES + (isX ? 0 : OP_BYTES);  // XJ/YJ

    // fragment loader for one kk granule (kk in 0,16,32,48)
    auto load_frags = [&](int kk, uint32_t av[2][4], uint32_t bv[2][4]) {
      const uint32_t a_sw = (uint32_t)((((kk >> 3) + a_kc) ^ (a_r & 7)) << 4);
      ldm_x4(av[0][0], av[0][1], av[0][2], av[0][3], i_b + a_r * 128 + a_sw);
      ldm_x4(av[1][0], av[1][1], av[1][2], av[1][3],
             i_b + (a_r + 16) * 128 + a_sw);
#pragma unroll
      for (int g = 0; g < 2; g++) {
        const int brow = wn * 32 + g * 16 + b_r;
        const uint32_t b_sw =
            (uint32_t)((((kk >> 3) + b_kc) ^ (brow & 7)) << 4);
        ldm_x4(bv[g][0], bv[g][1], bv[g][2], bv[g][3],
               j_b + brow * 128 + b_sw);
      }
    };

    // software pipeline over the 4 kk granules (double-buffered fragments)
    uint32_t av[2][2][4], bv[2][2][4];
    load_frags(0, av[0], bv[0]);
#pragma unroll
    for (int kp = 0; kp < 4; kp++) {
      const int cur = kp & 1;
      const int nxt = cur ^ 1;
      if (kp < 3) load_frags((kp + 1) * 16, av[nxt], bv[nxt]);
#pragma unroll
      for (int mf = 0; mf < 2; mf++)
#pragma unroll
        for (int g = 0; g < 2; g++) {
          mma_bf16(&acc[mf][2 * g + 0][0], av[cur][mf], &bv[cur][g][0]);
          mma_bf16(&acc[mf][2 * g + 1][0], av[cur][mf], &bv[cur][g][2]);
        }
    }

    if ((s & 7) == 7) {
      // ---- tile epilogue with A/B pairing via smem exchange ----
      const int t_glob = bx + (s >> 3) * GRID;
      __syncthreads();  // all warps done with buffer s%3 LDSM reads
      float *ex = reinterpret_cast<float *>(
                      smem_raw + (s % NSTAGE) * STAGE_BYTES) +
                  widg * EX_SLAB;

      if (!isX) {
        // Y-warps: stage B accumulators (row-padded [32][33] layout)
#pragma unroll
        for (int mf = 0; mf < 2; mf++)
#pragma unroll
          for (int n = 0; n < 4; n++)
#pragma unroll
            for (int h = 0; h < 2; h++)
#pragma unroll
              for (int cc = 0; cc < 2; cc++) {
                const int r32 = mf * 16 + h * 8 + (lane >> 2);
                const int c32 = n * 8 + 2 * (lane & 3) + cc;
                ex[r32 * 33 + c32] = acc[mf][n][2 * h + cc];
              }
      }
      __syncthreads();

      if (isX) {
        // X-warps: pair A (regs) with B (smem); row + col partial sums.
        // logits a=-A, b=-B (bounded, fixed shift 0):
        //   t1=e^{-A}, t2=e^{-A}(B-A), t3=e^{-B}
        float ra[4][3];   // per (mf*2+h) fragment row
        float ca[4][2][3];  // per (n, cc) fragment col
#pragma unroll
        for (int u = 0; u < 4; u++)
#pragma unroll
          for (int q = 0; q < 3; q++) ra[u][q] = 0.f;
#pragma unroll
        for (int n = 0; n < 4; n++)
#pragma unroll
          for (int cc = 0; cc < 2; cc++)
#pragma unroll
            for (int q = 0; q < 3; q++) ca[n][cc][q] = 0.f;

#pragma unroll
        for (int mf = 0; mf < 2; mf++)
#pragma unroll
          for (int n = 0; n < 4; n++)
#pragma unroll
            for (int h = 0; h < 2; h++)
#pragma unroll
              for (int cc = 0; cc < 2; cc++) {
                const int r32 = mf * 16 + h * 8 + (lane >> 2);
                const int c32 = n * 8 + 2 * (lane & 3) + cc;
                const float A = acc[mf][n][2 * h + cc];
                const float B = ex[r32 * 33 + c32];
                const float e = __expf(-A);
                const float t2 = e * (B - A);
                const float e2 = __expf(-B);
                ra[mf * 2 + h][0] += e;
                ra[mf * 2 + h][1] += t2;
                ra[mf * 2 + h][2] += e2;
                ca[n][cc][0] += e;
                ca[n][cc][1] += t2;
                ca[n][cc][2] += e2;
              }

        // row sums: reduce over the 4 quad lanes (cols)
#pragma unroll
        for (int u = 0; u < 4; u++)
#pragma unroll
          for (int q = 0; q < 3; q++) {
            ra[u][q] += __shfl_xor_sync(0xffffffffu, ra[u][q], 1);
            ra[u][q] += __shfl_xor_sync(0xffffffffu, ra[u][q], 2);
          }
        // col sums: reduce over the 8 row-quads (lane strides 4,8,16)
#pragma unroll
        for (int n = 0; n < 4; n++)
#pragma unroll
          for (int cc = 0; cc < 2; cc++)
#pragma unroll
            for (int q = 0; q < 3; q++) {
              ca[n][cc][q] += __shfl_xor_sync(0xffffffffu, ca[n][cc][q], 4);
              ca[n][cc][q] += __shfl_xor_sync(0xffffffffu, ca[n][cc][q], 8);
              ca[n][cc][q] += __shfl_xor_sync(0xffffffffu, ca[n][cc][q], 16);
            }

        if ((lane & 3) == 0) {
#pragma unroll
          for (int mf = 0; mf < 2; mf++)
#pragma unroll
            for (int h = 0; h < 2; h++) {
              const int rw = wm * 32 + mf * 16 + h * 8 + (lane >> 2);
              float *dst = &g_rowpart[((t_glob * 2 + wn) * BT + rw) * 3];
              dst[0] = ra[mf * 2 + h][0];
              dst[1] = ra[mf * 2 + h][1];
              dst[2] = ra[mf * 2 + h][2];
            }
        }
        if (lane < 4) {
#pragma unroll
          for (int n = 0; n < 4; n++)
#pragma unroll
            for (int cc = 0; cc < 2; cc++) {
              const int cl = wn * 32 + n * 8 + 2 * lane + cc;
              float *dst = &g_colpart[((t_glob * 2 + wm) * BT + cl) * 3];
              dst[0] = ca[n][cc][0];
              dst[1] = ca[n][cc][1];
              dst[2] = ca[n][cc][2];
            }
        }
      }
      // clear accumulators (both warp groups)
#pragma unroll
      for (int mf = 0; mf < 2; mf++)
#pragma unroll
        for (int n = 0; n < 4; n++)
#pragma unroll
          for (int r = 0; r < 4; r++) acc[mf][n][r] = 0.f;
      // buffer s%3 rewrite is guarded by the top-of-loop __syncthreads
    }
  }
}

// -------- 3) merge per-row partials + fused deterministic mean ----------
// 128 blocks x 256 threads; 8 threads cooperate per row (32 rows per block).
__global__ void merge_reduce_kernel(float *__restrict__ out) {
  __shared__ float red[32];
  const int tid = threadIdx.x;
  const int lane = tid & 31;
  const int q = tid & 7;                       // slot phase within row group
  const int r = blockIdx.x * 32 + (tid >> 3);  // global row
  const int I = r >> 6;
  const int ri = r & 63;
  float L = 0.f, S = 0.f, Lb = 0.f;

  // row-side contributions: tiles (I, J) for J >= I; 2 slots per tile
  const int cnt1 = 2 * (NIB - I);
  const int tb = tri_base(I);
  for (int u = q; u < cnt1; u += 8) {
    const int t = tb + (u >> 1);
    const int w = u & 1;
    const float *p = &g_rowpart[((t * 2 + w) * BT + ri) * 3];
    L += p[0];
    S += p[1];
    Lb += p[2];
  }
  // col-side contributions: tiles (K, I) for K < I; 2 slots per tile
  const int cnt2 = 2 * I;
  for (int u = q; u < cnt2; u += 8) {
    const int K = u >> 1;
    const int w = u & 1;
    const int tt = tri_base(K) + (I - K);
    const float *p = &g_colpart[((tt * 2 + w) * BT + ri) * 3];
    L += p[0];
    S += p[1];
    Lb += p[2];
  }

  // 8-lane segmented reduce (fixed order)
#pragma unroll
  for (int o = 1; o <= 4; o <<= 1) {
    L += __shfl_xor_sync(0xffffffffu, L, o);
    S += __shfl_xor_sync(0xffffffffu, S, o);
    Lb += __shfl_xor_sync(0xffffffffu, Lb, o);
  }

  // group leader: kl_r = sum t*(a-b) - lse(a) + lse(b), fixed shift 0
  float kl = 0.f;
  if (q == 0) kl = S / L - logf(L) + logf(Lb);
  // warp: sum the 4 leaders' kl values (lanes 0,8,16,24), fixed order
#pragma unroll
  for (int o = 8; o <= 16; o <<= 1) kl += __shfl_xor_sync(0xffffffffu, kl, o);
  if (lane == 0) red[tid >> 5] = kl;
  __syncthreads();

  // warp 0: sum 8 warp partials (fixed order), then last-block combine
  if (tid < 32) {
    float v = (lane < 8) ? red[lane] : 0.f;
#pragma unroll
    for (int o = 1; o <= 4; o <<= 1) v += __shfl_xor_sync(0xffffffffu, v, o);
    if (lane == 0) {
      g_bsum[blockIdx.x] = v;
      __threadfence();
      const int prev = atomicAdd(&g_ctr, 1);
      if (prev == MR_BLOCKS - 1) {  // last block: finish the mean
        float s = 0.f;
        for (int k = 0; k < MR_BLOCKS; k++) {
          s += *((volatile float *)&g_bsum[k]);
        }
        out[0] = s / (float)NROW;
        atomicExch(&g_ctr, 0);  // reset for next graph replay
      }
    }
  }
}

// ---------------- launch ----------------
extern "C" void kernel_launch(void *const *d_in, const int *in_sizes, int n_in,
                              void *d_out, int out_size) {
  const float *X = (const float *)d_in[0];  // cosine_distance_latent (target)
  const float *Y = (const float *)d_in[1];  // mse_latent (predicted)
  float *out = (float *)d_out;

  cudaFuncSetAttribute(gram_kl_kernel,
                       cudaFuncAttributeMaxDynamicSharedMemorySize, SMEM_TOTAL);

  normalize_kernel<<<1024, 256>>>(X, Y);
  gram_kl_kernel<<<GRID, 256, SMEM_TOTAL>>>();
  merge_reduce_kernel<<<MR_BLOCKS, 256>>>(out);
}